// round 4
// baseline (speedup 1.0000x reference)
#include <cuda_runtime.h>

#define E_TOT   40000
#define N_NODES 4000
#define NCOEF   25
#define HID     64
#define FIN     128
#define F3      640

// ---------------- scratch (device globals; no allocs allowed) ----------------
__device__ __align__(16) float g_m0[(long long)E_TOT * F3]; // 102.4 MB
__device__ int   g_cnt[N_NODES];
__device__ int   g_off[N_NODES + 1];
__device__ int   g_cur[N_NODES];
__device__ int   g_list[E_TOT];

// ---------------- small helpers ----------------
__device__ __forceinline__ unsigned long long pack2(float x) {
    unsigned long long r;
    asm("mov.b64 %0, {%1, %1};" : "=l"(r) : "f"(x));
    return r;
}
__device__ __forceinline__ unsigned long long pack_pair(float lo, float hi) {
    unsigned long long r;
    asm("mov.b64 %0, {%1, %2};" : "=l"(r) : "f"(lo), "f"(hi));
    return r;
}
__device__ __forceinline__ void unpack2(unsigned long long v, float& lo, float& hi) {
    asm("mov.b64 {%0, %1}, %2;" : "=f"(lo), "=f"(hi) : "l"(v));
}
__device__ __forceinline__ void fma2(unsigned long long& c, unsigned long long a,
                                     unsigned long long b) {
    asm("fma.rn.f32x2 %0, %1, %2, %0;" : "+l"(c) : "l"(a), "l"(b));
}
__device__ __forceinline__ float allred16(float v) {
    v += __shfl_xor_sync(0xffffffffu, v, 8, 16);
    v += __shfl_xor_sync(0xffffffffu, v, 4, 16);
    v += __shfl_xor_sync(0xffffffffu, v, 2, 16);
    v += __shfl_xor_sync(0xffffffffu, v, 1, 16);
    return v;
}

#define CP_ASYNC16(dst, src) \
    asm volatile("cp.async.cg.shared.global [%0], [%1], 16;" :: "r"(dst), "l"(src))
#define CP_ASYNC4(dst, src) \
    asm volatile("cp.async.ca.shared.global [%0], [%1], 4;" :: "r"(dst), "l"(src))
#define CP_COMMIT() asm volatile("cp.async.commit_group;")
#define CP_WAIT(n)  asm volatile("cp.async.wait_group %0;" :: "n"(n))

// ---------------- edge-list building ----------------
__global__ void k_zero() {
    int i = blockIdx.x * blockDim.x + threadIdx.x;
    if (i < N_NODES) g_cnt[i] = 0;
}

__global__ void k_count(const int* __restrict__ ei, const int* __restrict__ noff) {
    int e = blockIdx.x * blockDim.x + threadIdx.x;
    if (e < E_TOT) {
        int d = ei[E_TOT + e] - noff[0];
        atomicAdd(&g_cnt[d], 1);
    }
}

__global__ void __launch_bounds__(1024) k_scan() {
    __shared__ int s[1024];
    const int tid = threadIdx.x;
    int v[4];
    int tot = 0;
#pragma unroll
    for (int j = 0; j < 4; j++) {
        int idx = tid * 4 + j;
        v[j] = (idx < N_NODES) ? g_cnt[idx] : 0;
        tot += v[j];
    }
    s[tid] = tot;
    __syncthreads();
    for (int off = 1; off < 1024; off <<= 1) {
        int t = (tid >= off) ? s[tid - off] : 0;
        __syncthreads();
        s[tid] += t;
        __syncthreads();
    }
    int run = s[tid] - tot;  // exclusive
#pragma unroll
    for (int j = 0; j < 4; j++) {
        int idx = tid * 4 + j;
        if (idx < N_NODES) {
            g_off[idx] = run;
            g_cur[idx] = run;
        }
        run += v[j];
    }
    if (tid == 1023) g_off[N_NODES] = s[1023];
}

__global__ void k_fill(const int* __restrict__ ei, const int* __restrict__ noff) {
    int e = blockIdx.x * blockDim.x + threadIdx.x;
    if (e < E_TOT) {
        int d = ei[E_TOT + e] - noff[0];
        int pos = atomicAdd(&g_cur[d], 1);
        g_list[pos] = e;
    }
}

// ---------------- fused MLP: (Lin->LN->SiLU)x2 then Lin3 + env, all in one CTA ----
// CTA: 64 edges, 256 threads.
// Phase A thread map: eg4 = tid>>4 (4 edges each), fg4 = tid&15 (4 feats each)
// Phase B thread map: eg  = tid&7  (8 edges: eg+8r), fg = tid>>3 (4 cols)
__global__ void __launch_bounds__(256) k_mlp(
    const float* __restrict__ x_edge, const float* __restrict__ edge_distance,
    const float* __restrict__ w1, const float* __restrict__ b1,
    const float* __restrict__ g1, const float* __restrict__ be1,
    const float* __restrict__ w2, const float* __restrict__ b2,
    const float* __restrict__ g2, const float* __restrict__ be2,
    const float* __restrict__ w3, const float* __restrict__ b3) {
    __shared__ __align__(16) float sbuf[64 * 132];  // 33792 B
    // aliases inside sbuf:
    float* s_xe = sbuf;                 // stride 132 (phase A input)
    float* s_h  = sbuf;                 // stride 68 (h1 then h2)
    float* s_w3 = sbuf + 64 * 68;       // 32*128 floats = 16384 B (phase B)
    __shared__ __align__(16) float s_env[64];

    const int tid = threadIdx.x;
    const int e0 = blockIdx.x * 64;

    {   // load x_edge tile [64][128] -> padded smem
        const float4* src = reinterpret_cast<const float4*>(x_edge + (long long)e0 * FIN);
#pragma unroll
        for (int i = tid; i < 64 * 32; i += 256) {
            int e = i >> 5, k4 = i & 31;
            float4 v = src[i];
            *reinterpret_cast<float4*>(&s_xe[e * 132 + k4 * 4]) = v;
        }
    }
    if (tid < 64) {
        float d = edge_distance[e0 + tid] * (1.0f / 12.0f);
        float env = 0.f;
        if (d < 1.f) {
            float d2 = d * d, d4 = d2 * d2, d5 = d4 * d;
            env = 1.f + d5 * (-21.f + d * 35.f - d2 * 15.f);
        }
        s_env[tid] = env * 0.2f;  // env / RESCALE
    }
    __syncthreads();

    const int fg4 = tid & 15;
    const int eg4 = tid >> 4;

    float b1a[4], g1a[4], be1a[4], b2a[4], g2a[4], be2a[4];
#pragma unroll
    for (int j = 0; j < 4; j++) {
        b1a[j]  = __ldg(b1 + fg4 * 4 + j);
        g1a[j]  = __ldg(g1 + fg4 * 4 + j);
        be1a[j] = __ldg(be1 + fg4 * 4 + j);
        b2a[j]  = __ldg(b2 + fg4 * 4 + j);
        g2a[j]  = __ldg(g2 + fg4 * 4 + j);
        be2a[j] = __ldg(be2 + fg4 * 4 + j);
    }

    // -------- layer 1 (packed f32x2) --------
    unsigned long long acc1[4][2] = {};
    for (int k = 0; k < 128; k++) {
        float4 b = __ldg(reinterpret_cast<const float4*>(w1 + k * 64 + fg4 * 4));
        unsigned long long b0 = pack_pair(b.x, b.y), bq = pack_pair(b.z, b.w);
#pragma unroll
        for (int r = 0; r < 4; r++) {
            unsigned long long a2 = pack2(s_xe[(eg4 * 4 + r) * 132 + k]);
            fma2(acc1[r][0], a2, b0);
            fma2(acc1[r][1], a2, bq);
        }
    }
    float h1v[4][4];
#pragma unroll
    for (int r = 0; r < 4; r++) {
        float hv[4], s1 = 0.f;
        unpack2(acc1[r][0], hv[0], hv[1]);
        unpack2(acc1[r][1], hv[2], hv[3]);
#pragma unroll
        for (int j = 0; j < 4; j++) { hv[j] += b1a[j]; s1 += hv[j]; }
        s1 = allred16(s1);
        float mu = s1 * (1.f / 64.f);
        float s2 = 0.f;
#pragma unroll
        for (int j = 0; j < 4; j++) { float d = hv[j] - mu; s2 += d * d; }
        s2 = allred16(s2);
        float rstd = rsqrtf(s2 * (1.f / 64.f) + 1e-5f);
#pragma unroll
        for (int j = 0; j < 4; j++) {
            float y = (hv[j] - mu) * rstd * g1a[j] + be1a[j];
            h1v[r][j] = y / (1.f + __expf(-y));  // SiLU
        }
    }
    __syncthreads();  // s_xe reads done
#pragma unroll
    for (int r = 0; r < 4; r++)
#pragma unroll
        for (int j = 0; j < 4; j++) s_h[(eg4 * 4 + r) * 68 + fg4 * 4 + j] = h1v[r][j];
    __syncthreads();

    // -------- layer 2 (packed f32x2) --------
    unsigned long long acc2[4][2] = {};
    for (int k = 0; k < 64; k++) {
        float4 b = __ldg(reinterpret_cast<const float4*>(w2 + k * 64 + fg4 * 4));
        unsigned long long b0 = pack_pair(b.x, b.y), bq = pack_pair(b.z, b.w);
#pragma unroll
        for (int r = 0; r < 4; r++) {
            unsigned long long a2 = pack2(s_h[(eg4 * 4 + r) * 68 + k]);
            fma2(acc2[r][0], a2, b0);
            fma2(acc2[r][1], a2, bq);
        }
    }
    __syncthreads();  // all h1 reads done before overwriting
    float h2v[4][4];
#pragma unroll
    for (int r = 0; r < 4; r++) {
        float hv[4], s1 = 0.f;
        unpack2(acc2[r][0], hv[0], hv[1]);
        unpack2(acc2[r][1], hv[2], hv[3]);
#pragma unroll
        for (int j = 0; j < 4; j++) { hv[j] += b2a[j]; s1 += hv[j]; }
        s1 = allred16(s1);
        float mu = s1 * (1.f / 64.f);
        float s2 = 0.f;
#pragma unroll
        for (int j = 0; j < 4; j++) { float d = hv[j] - mu; s2 += d * d; }
        s2 = allred16(s2);
        float rstd = rsqrtf(s2 * (1.f / 64.f) + 1e-5f);
#pragma unroll
        for (int j = 0; j < 4; j++) {
            float y = (hv[j] - mu) * rstd * g2a[j] + be2a[j];
            h2v[r][j] = y / (1.f + __expf(-y));
        }
    }
#pragma unroll
    for (int r = 0; r < 4; r++)
#pragma unroll
        for (int j = 0; j < 4; j++) s_h[(eg4 * 4 + r) * 68 + fg4 * 4 + j] = h2v[r][j];

    // -------- layer 3: [64e][640f] = h[64x64] @ w3[64x640], f32x2 --------
    const int eg = tid & 7;
    const int fg = tid >> 3;  // 0..31

#pragma unroll 1
    for (int fc = 0; fc < 5; fc++) {
        unsigned long long acc[8][2];
        {
            float4 bb = __ldg(reinterpret_cast<const float4*>(b3 + fc * 128 + fg * 4));
            unsigned long long bp0 = pack_pair(bb.x, bb.y), bp1 = pack_pair(bb.z, bb.w);
#pragma unroll
            for (int r = 0; r < 8; r++) { acc[r][0] = bp0; acc[r][1] = bp1; }
        }
#pragma unroll 1
        for (int kc = 0; kc < 2; kc++) {
            __syncthreads();  // previous s_w3 reads / h writes done
            for (int i = tid; i < 32 * 32; i += 256) {
                int k = i >> 5, f4 = i & 31;
                float4 v = __ldg(reinterpret_cast<const float4*>(
                    w3 + (long long)(kc * 32 + k) * 640 + fc * 128 + f4 * 4));
                *reinterpret_cast<float4*>(&s_w3[k * 128 + f4 * 4]) = v;
            }
            __syncthreads();
#pragma unroll 4
            for (int k = 0; k < 32; k++) {
                unsigned long long b0 = *reinterpret_cast<const unsigned long long*>(
                    &s_w3[k * 128 + fg * 4]);
                unsigned long long b1 = *reinterpret_cast<const unsigned long long*>(
                    &s_w3[k * 128 + fg * 4 + 2]);
#pragma unroll
                for (int r = 0; r < 8; r++) {
                    unsigned long long a2 = pack2(s_h[(eg + 8 * r) * 68 + kc * 32 + k]);
                    fma2(acc[r][0], a2, b0);
                    fma2(acc[r][1], a2, b1);
                }
            }
        }
#pragma unroll
        for (int r = 0; r < 8; r++) {
            int el = eg + 8 * r;
            float s = s_env[el];
            float4 v;
            float lo, hi;
            unpack2(acc[r][0], lo, hi); v.x = lo * s; v.y = hi * s;
            unpack2(acc[r][1], lo, hi); v.z = lo * s; v.w = hi * s;
            *reinterpret_cast<float4*>(
                &g_m0[(long long)(e0 + el) * 640 + fc * 128 + fg * 4]) = v;
        }
    }
}

// ---------------- K3: per-node gather, cp.async double-buffered ----------------
// out[n,i,c] = x[n,i,c] + sum_{e in edges(n)} sum_k wig[e,i,k(k+1)] * m0[e,k,c]
// CTA per node, 160 threads: iq = tid>>5 (5 rows), cq = tid&31 (4 cols)
__global__ void __launch_bounds__(160) k_gather(
    const float* __restrict__ x, const float* __restrict__ wig,
    float* __restrict__ out) {
    __shared__ __align__(16) float s_m0[2][640];  // [k][c]
    __shared__ __align__(16) float s_w[2][128];   // [k*25+i] (125 used)
    const int n = blockIdx.x;
    const int tid = threadIdx.x;
    const int iq = tid >> 5;
    const int cq = tid & 31;
    const int wk = tid / 25;          // for wig fetch (tid < 125)
    const int wi = tid - wk * 25;
    const bool wact = tid < 125;
    const long long wig_off = (long long)wi * 25 + wk * (wk + 1);

    unsigned int sm0[2], sw[2];
    sm0[0] = (unsigned int)__cvta_generic_to_shared(&s_m0[0][tid * 4]);
    sm0[1] = (unsigned int)__cvta_generic_to_shared(&s_m0[1][tid * 4]);
    sw[0]  = (unsigned int)__cvta_generic_to_shared(&s_w[0][tid]);
    sw[1]  = (unsigned int)__cvta_generic_to_shared(&s_w[1][tid]);

    const int beg = g_off[n], end = g_off[n + 1];
    unsigned long long acc[5][2] = {};

    if (beg < end) {
        int e = g_list[beg];
        CP_ASYNC16(sm0[0], &g_m0[(long long)e * 640 + tid * 4]);
        if (wact) CP_ASYNC4(sw[0], &wig[(long long)e * 625 + wig_off]);
        CP_COMMIT();
    }
    for (int t = beg; t < end; t++) {
        const int s = (t - beg) & 1;
        if (t + 1 < end) {
            int e = g_list[t + 1];
            CP_ASYNC16(sm0[s ^ 1], &g_m0[(long long)e * 640 + tid * 4]);
            if (wact) CP_ASYNC4(sw[s ^ 1], &wig[(long long)e * 625 + wig_off]);
            CP_COMMIT();
            CP_WAIT(1);
        } else {
            CP_WAIT(0);
        }
        __syncthreads();
#pragma unroll
        for (int k = 0; k < 5; k++) {
            unsigned long long b0 = *reinterpret_cast<const unsigned long long*>(
                &s_m0[s][k * 128 + cq * 4]);
            unsigned long long b1 = *reinterpret_cast<const unsigned long long*>(
                &s_m0[s][k * 128 + cq * 4 + 2]);
#pragma unroll
            for (int r = 0; r < 5; r++) {
                unsigned long long a2 = pack2(s_w[s][k * 25 + iq * 5 + r]);
                fma2(acc[r][0], a2, b0);
                fma2(acc[r][1], a2, b1);
            }
        }
        __syncthreads();  // protect buf s before it is re-staged
    }
#pragma unroll
    for (int r = 0; r < 5; r++) {
        int i = iq * 5 + r;
        long long off = ((long long)n * 25 + i) * 128 + cq * 4;
        float4 xv = *reinterpret_cast<const float4*>(&x[off]);
        float4 o;
        float lo, hi;
        unpack2(acc[r][0], lo, hi); o.x = xv.x + lo; o.y = xv.y + hi;
        unpack2(acc[r][1], lo, hi); o.z = xv.z + lo; o.w = xv.w + hi;
        *reinterpret_cast<float4*>(&out[off]) = o;
    }
}

// ---------------- launch ----------------
extern "C" void kernel_launch(void* const* d_in, const int* in_sizes, int n_in,
                              void* d_out, int out_size) {
    const float* x   = (const float*)d_in[0];
    const float* xe  = (const float*)d_in[1];
    const float* ed  = (const float*)d_in[2];
    const float* wig = (const float*)d_in[3];
    const int*   ei  = (const int*)d_in[4];
    const float* w1  = (const float*)d_in[5];
    const float* b1  = (const float*)d_in[6];
    const float* g1  = (const float*)d_in[7];
    const float* be1 = (const float*)d_in[8];
    const float* w2  = (const float*)d_in[9];
    const float* b2  = (const float*)d_in[10];
    const float* g2  = (const float*)d_in[11];
    const float* be2 = (const float*)d_in[12];
    const float* w3  = (const float*)d_in[13];
    const float* b3  = (const float*)d_in[14];
    const int* noff  = (const int*)d_in[15];
    float* out = (float*)d_out;

    k_zero<<<(N_NODES + 255) / 256, 256>>>();
    k_count<<<(E_TOT + 255) / 256, 256>>>(ei, noff);
    k_scan<<<1, 1024>>>();
    k_fill<<<(E_TOT + 255) / 256, 256>>>(ei, noff);
    k_mlp<<<E_TOT / 64, 256>>>(xe, ed, w1, b1, g1, be1, w2, b2, g2, be2, w3, b3);
    k_gather<<<N_NODES, 160>>>(x, wig, out);
    (void)in_sizes; (void)n_in; (void)out_size;
}

// round 11
// speedup vs baseline: 1.0101x; 1.0101x over previous
#include <cuda_runtime.h>

#define E_TOT   40000
#define N_NODES 4000
#define NCOEF   25
#define HID     64
#define FIN     128
#define F3      640

// ---------------- scratch (device globals; no allocs allowed) ----------------
__device__ __align__(16) float g_m0[(long long)E_TOT * F3]; // 102.4 MB
__device__ int   g_cnt[N_NODES];
__device__ int   g_off[N_NODES + 1];
__device__ int   g_list[E_TOT];

// ---------------- small helpers ----------------
__device__ __forceinline__ unsigned long long pack2(float x) {
    unsigned long long r;
    asm("mov.b64 %0, {%1, %1};" : "=l"(r) : "f"(x));
    return r;
}
__device__ __forceinline__ unsigned long long pack_pair(float lo, float hi) {
    unsigned long long r;
    asm("mov.b64 %0, {%1, %2};" : "=l"(r) : "f"(lo), "f"(hi));
    return r;
}
__device__ __forceinline__ void unpack2(unsigned long long v, float& lo, float& hi) {
    asm("mov.b64 {%0, %1}, %2;" : "=f"(lo), "=f"(hi) : "l"(v));
}
__device__ __forceinline__ void fma2(unsigned long long& c, unsigned long long a,
                                     unsigned long long b) {
    asm("fma.rn.f32x2 %0, %1, %2, %0;" : "+l"(c) : "l"(a), "l"(b));
}
__device__ __forceinline__ float allred16(float v) {
    v += __shfl_xor_sync(0xffffffffu, v, 8, 16);
    v += __shfl_xor_sync(0xffffffffu, v, 4, 16);
    v += __shfl_xor_sync(0xffffffffu, v, 2, 16);
    v += __shfl_xor_sync(0xffffffffu, v, 1, 16);
    return v;
}

#define CP_ASYNC16(dst, src) \
    asm volatile("cp.async.cg.shared.global [%0], [%1], 16;" :: "r"(dst), "l"(src))
#define CP_ASYNC4(dst, src) \
    asm volatile("cp.async.ca.shared.global [%0], [%1], 4;" :: "r"(dst), "l"(src))
#define CP_COMMIT() asm volatile("cp.async.commit_group;")
#define CP_WAIT(n)  asm volatile("cp.async.wait_group %0;" :: "n"(n))

// ---------------- edge-list building ----------------
__global__ void k_zero() {
    int i = blockIdx.x * blockDim.x + threadIdx.x;
    if (i < N_NODES) g_cnt[i] = 0;
}

__global__ void k_count(const int* __restrict__ ei, const int* __restrict__ noff) {
    int e = blockIdx.x * blockDim.x + threadIdx.x;
    if (e < E_TOT) {
        int d = ei[E_TOT + e] - noff[0];
        atomicAdd(&g_cnt[d], 1);
    }
}

// single-CTA: exclusive scan of counts -> g_off, then fill g_list via smem cursors
__global__ void __launch_bounds__(1024) k_scanfill(
    const int* __restrict__ ei, const int* __restrict__ noff) {
    __shared__ int s[1024];
    __shared__ int s_cur[N_NODES];
    const int tid = threadIdx.x;
    int v[4];
    int tot = 0;
#pragma unroll
    for (int j = 0; j < 4; j++) {
        int idx = tid * 4 + j;
        v[j] = (idx < N_NODES) ? g_cnt[idx] : 0;
        tot += v[j];
    }
    s[tid] = tot;
    __syncthreads();
    for (int off = 1; off < 1024; off <<= 1) {
        int t = (tid >= off) ? s[tid - off] : 0;
        __syncthreads();
        s[tid] += t;
        __syncthreads();
    }
    int run = s[tid] - tot;  // exclusive
#pragma unroll
    for (int j = 0; j < 4; j++) {
        int idx = tid * 4 + j;
        if (idx < N_NODES) {
            g_off[idx] = run;
            s_cur[idx] = run;
        }
        run += v[j];
    }
    if (tid == 1023) g_off[N_NODES] = s[1023];
    __syncthreads();
    const int nf = noff[0];
    for (int e = tid; e < E_TOT; e += 1024) {
        int d = ei[E_TOT + e] - nf;
        int pos = atomicAdd(&s_cur[d], 1);
        g_list[pos] = e;
    }
}

// ---------------- fused MLP: (Lin->LN->SiLU)x2 then Lin3 + env ----------------
// CTA: 64 edges, 256 threads.
// Phase A map: eg4 = tid>>4 (4 edges), fg4 = tid&15 (4 feats)
// Phase B map: pair base eg = tid&7 (pairs eg+8p, p=0..3 -> 8 edges), fg = tid>>3 (4 f)
__global__ void __launch_bounds__(256, 3) k_mlp(
    const float* __restrict__ x_edge, const float* __restrict__ edge_distance,
    const float* __restrict__ w1, const float* __restrict__ b1,
    const float* __restrict__ g1, const float* __restrict__ be1,
    const float* __restrict__ w2, const float* __restrict__ b2,
    const float* __restrict__ g2, const float* __restrict__ be2,
    const float* __restrict__ w3, const float* __restrict__ b3) {
    // layout: [0, 8448)   : s_xe (stride 132) / s_h (stride 68) in phase A
    //         [0, 4224)   : s_ht transposed h2 [k][e] stride 66 in phase B
    //         [4224,10368): s_w3 3 buffers of 16x128
    __shared__ __align__(16) float sbuf[10368];  // 41472 B
    __shared__ __align__(16) float s_env[64];
    float* s_xe = sbuf;
    float* s_h  = sbuf;
    float* s_ht = sbuf;
    float* s_w3 = sbuf + 4224;

    const int tid = threadIdx.x;
    const int e0 = blockIdx.x * 64;

    {   // load x_edge tile [64][128] -> padded smem
        const float4* src = reinterpret_cast<const float4*>(x_edge + (long long)e0 * FIN);
#pragma unroll
        for (int i = tid; i < 64 * 32; i += 256) {
            int e = i >> 5, k4 = i & 31;
            float4 v = src[i];
            *reinterpret_cast<float4*>(&s_xe[e * 132 + k4 * 4]) = v;
        }
    }
    if (tid < 64) {
        float d = edge_distance[e0 + tid] * (1.0f / 12.0f);
        float env = 0.f;
        if (d < 1.f) {
            float d2 = d * d, d4 = d2 * d2, d5 = d4 * d;
            env = 1.f + d5 * (-21.f + d * 35.f - d2 * 15.f);
        }
        s_env[tid] = env * 0.2f;  // env / RESCALE
    }
    __syncthreads();

    const int fg4 = tid & 15;
    const int eg4 = tid >> 4;

    float b1a[4], g1a[4], be1a[4], b2a[4], g2a[4], be2a[4];
#pragma unroll
    for (int j = 0; j < 4; j++) {
        b1a[j]  = __ldg(b1 + fg4 * 4 + j);
        g1a[j]  = __ldg(g1 + fg4 * 4 + j);
        be1a[j] = __ldg(be1 + fg4 * 4 + j);
        b2a[j]  = __ldg(b2 + fg4 * 4 + j);
        g2a[j]  = __ldg(g2 + fg4 * 4 + j);
        be2a[j] = __ldg(be2 + fg4 * 4 + j);
    }

    // -------- layer 1 --------
    unsigned long long acc1[4][2] = {};
    for (int k = 0; k < 128; k++) {
        float4 b = __ldg(reinterpret_cast<const float4*>(w1 + k * 64 + fg4 * 4));
        unsigned long long b0 = pack_pair(b.x, b.y), bq = pack_pair(b.z, b.w);
#pragma unroll
        for (int r = 0; r < 4; r++) {
            unsigned long long a2 = pack2(s_xe[(eg4 * 4 + r) * 132 + k]);
            fma2(acc1[r][0], a2, b0);
            fma2(acc1[r][1], a2, bq);
        }
    }
    float h1v[4][4];
#pragma unroll
    for (int r = 0; r < 4; r++) {
        float hv[4], s1 = 0.f;
        unpack2(acc1[r][0], hv[0], hv[1]);
        unpack2(acc1[r][1], hv[2], hv[3]);
#pragma unroll
        for (int j = 0; j < 4; j++) { hv[j] += b1a[j]; s1 += hv[j]; }
        s1 = allred16(s1);
        float mu = s1 * (1.f / 64.f);
        float s2 = 0.f;
#pragma unroll
        for (int j = 0; j < 4; j++) { float d = hv[j] - mu; s2 += d * d; }
        s2 = allred16(s2);
        float rstd = rsqrtf(s2 * (1.f / 64.f) + 1e-5f);
#pragma unroll
        for (int j = 0; j < 4; j++) {
            float y = (hv[j] - mu) * rstd * g1a[j] + be1a[j];
            h1v[r][j] = y / (1.f + __expf(-y));  // SiLU
        }
    }
    __syncthreads();  // s_xe reads done
#pragma unroll
    for (int r = 0; r < 4; r++)
#pragma unroll
        for (int j = 0; j < 4; j++) s_h[(eg4 * 4 + r) * 68 + fg4 * 4 + j] = h1v[r][j];
    __syncthreads();

    // -------- layer 2 --------
    unsigned long long acc2[4][2] = {};
    for (int k = 0; k < 64; k++) {
        float4 b = __ldg(reinterpret_cast<const float4*>(w2 + k * 64 + fg4 * 4));
        unsigned long long b0 = pack_pair(b.x, b.y), bq = pack_pair(b.z, b.w);
#pragma unroll
        for (int r = 0; r < 4; r++) {
            unsigned long long a2 = pack2(s_h[(eg4 * 4 + r) * 68 + k]);
            fma2(acc2[r][0], a2, b0);
            fma2(acc2[r][1], a2, bq);
        }
    }
    __syncthreads();  // all h1 reads done before overwriting

    // stage w3 chunk 0 while computing LN/SiLU of layer 2
    {
        int kr = tid >> 4, colq = tid & 15;
        const float* src = w3 + (long long)kr * 640 + colq * 8;
        unsigned int dst = (unsigned int)__cvta_generic_to_shared(
            &s_w3[kr * 128 + colq * 8]);
        CP_ASYNC16(dst, src);
        CP_ASYNC16(dst + 16, src + 4);
    }
    CP_COMMIT();

#pragma unroll
    for (int r = 0; r < 4; r++) {
        float hv[4], s1 = 0.f;
        unpack2(acc2[r][0], hv[0], hv[1]);
        unpack2(acc2[r][1], hv[2], hv[3]);
#pragma unroll
        for (int j = 0; j < 4; j++) { hv[j] += b2a[j]; s1 += hv[j]; }
        s1 = allred16(s1);
        float mu = s1 * (1.f / 64.f);
        float s2 = 0.f;
#pragma unroll
        for (int j = 0; j < 4; j++) { float d = hv[j] - mu; s2 += d * d; }
        s2 = allred16(s2);
        float rstd = rsqrtf(s2 * (1.f / 64.f) + 1e-5f);
#pragma unroll
        for (int j = 0; j < 4; j++) {
            float y = (hv[j] - mu) * rstd * g2a[j] + be2a[j];
            float sv = y / (1.f + __expf(-y));
            // transposed store: s_ht[k][e], k = fg4*4+j, e = eg4*4+r
            s_ht[(fg4 * 4 + j) * 66 + eg4 * 4 + r] = sv;
        }
    }
    // stage w3 chunk 1
    {
        int kr = tid >> 4, colq = tid & 15;
        const float* src = w3 + (long long)(16 + kr) * 640 + colq * 8;
        unsigned int dst = (unsigned int)__cvta_generic_to_shared(
            &s_w3[2048 + kr * 128 + colq * 8]);
        CP_ASYNC16(dst, src);
        CP_ASYNC16(dst + 16, src + 4);
    }
    CP_COMMIT();
    __syncthreads();

    // -------- layer 3: 20 chunks (fc 0..4 x kc 0..3), 3-buffer cp.async pipe ----
    const int eg = tid & 7;
    const int fg = tid >> 3;  // 0..31
    const int kr = tid >> 4, colq = tid & 15;

    unsigned long long acc[4][4];  // [pair p][feat j]
#pragma unroll 1
    for (int ci = 0; ci < 20; ci++) {
        const int fc = ci >> 2, kc = ci & 3, buf = ci % 3;
        if (kc == 0) {
            float4 bb = __ldg(reinterpret_cast<const float4*>(b3 + fc * 128 + fg * 4));
#pragma unroll
            for (int p = 0; p < 4; p++) {
                acc[p][0] = pack2(bb.x); acc[p][1] = pack2(bb.y);
                acc[p][2] = pack2(bb.z); acc[p][3] = pack2(bb.w);
            }
        }
        CP_WAIT(1);
        __syncthreads();
        if (ci + 2 < 20) {
            int ci2 = ci + 2;
            const float* src = w3 + (long long)((ci2 & 3) * 16 + kr) * 640
                               + (ci2 >> 2) * 128 + colq * 8;
            unsigned int dst = (unsigned int)__cvta_generic_to_shared(
                &s_w3[(ci2 % 3) * 2048 + kr * 128 + colq * 8]);
            CP_ASYNC16(dst, src);
            CP_ASYNC16(dst + 16, src + 4);
        }
        CP_COMMIT();
        const float* wb = s_w3 + buf * 2048;
#pragma unroll 4
        for (int k = 0; k < 16; k++) {
            unsigned long long wv0 = *reinterpret_cast<const unsigned long long*>(
                &wb[k * 128 + fg * 4]);
            unsigned long long wv1 = *reinterpret_cast<const unsigned long long*>(
                &wb[k * 128 + fg * 4 + 2]);
            float w0, w1f, w2f, w3f;
            unpack2(wv0, w0, w1f);
            unpack2(wv1, w2f, w3f);
            unsigned long long ws[4] = {pack2(w0), pack2(w1f), pack2(w2f), pack2(w3f)};
            const float* hrow = s_ht + (kc * 16 + k) * 66;
#pragma unroll
            for (int p = 0; p < 4; p++) {
                unsigned long long h2 = *reinterpret_cast<const unsigned long long*>(
                    &hrow[2 * (eg + 8 * p)]);
                fma2(acc[p][0], h2, ws[0]);
                fma2(acc[p][1], h2, ws[1]);
                fma2(acc[p][2], h2, ws[2]);
                fma2(acc[p][3], h2, ws[3]);
            }
        }
        if (kc == 3) {
#pragma unroll
            for (int p = 0; p < 4; p++) {
                int ep = 2 * (eg + 8 * p);
                float sa = s_env[ep], sb = s_env[ep + 1];
                float4 va, vb;
                float lo, hi;
                unpack2(acc[p][0], lo, hi); va.x = lo * sa; vb.x = hi * sb;
                unpack2(acc[p][1], lo, hi); va.y = lo * sa; vb.y = hi * sb;
                unpack2(acc[p][2], lo, hi); va.z = lo * sa; vb.z = hi * sb;
                unpack2(acc[p][3], lo, hi); va.w = lo * sa; vb.w = hi * sb;
                long long base = (long long)(e0 + ep) * 640 + fc * 128 + fg * 4;
                *reinterpret_cast<float4*>(&g_m0[base]) = va;
                *reinterpret_cast<float4*>(&g_m0[base + 640]) = vb;
            }
        }
    }
}

// ---------------- K3: per-node gather, depth-2 cp.async, 3 buffers ----------------
// out[n,i,c] = x[n,i,c] + sum_{e in edges(n)} sum_k wig[e,i,k(k+1)] * m0[e,k,c]
// CTA per node, 160 threads: iq = tid>>5 (5 rows), cq = tid&31 (4 cols)
__global__ void __launch_bounds__(160) k_gather(
    const float* __restrict__ x, const float* __restrict__ wig,
    float* __restrict__ out) {
    __shared__ __align__(16) float s_m0[3][640];  // [k][c]
    __shared__ __align__(16) float s_w[3][128];   // [k*25+i] (125 used)
    const int n = blockIdx.x;
    const int tid = threadIdx.x;
    const int iq = tid >> 5;
    const int cq = tid & 31;
    const int wk = tid / 25;
    const int wi = tid - wk * 25;
    const bool wact = tid < 125;
    const long long wig_off = (long long)wi * 25 + wk * (wk + 1);

    unsigned int sm0[3], sw[3];
#pragma unroll
    for (int b = 0; b < 3; b++) {
        sm0[b] = (unsigned int)__cvta_generic_to_shared(&s_m0[b][tid * 4]);
        sw[b]  = (unsigned int)__cvta_generic_to_shared(&s_w[b][tid]);
    }

    const int beg = g_off[n], end = g_off[n + 1];

    // init accumulators from x (folds the final add, overlaps the loads)
    unsigned long long acc[5][2];
#pragma unroll
    for (int r = 0; r < 5; r++) {
        long long off = ((long long)n * 25 + iq * 5 + r) * 128 + cq * 4;
        float4 xv = *reinterpret_cast<const float4*>(&x[off]);
        acc[r][0] = pack_pair(xv.x, xv.y);
        acc[r][1] = pack_pair(xv.z, xv.w);
    }

    // prologue: stage edges beg, beg+1 (commit always to keep group count aligned)
#pragma unroll
    for (int j = 0; j < 2; j++) {
        if (beg + j < end) {
            int e = g_list[beg + j];
            CP_ASYNC16(sm0[j], &g_m0[(long long)e * 640 + tid * 4]);
            if (wact) CP_ASYNC4(sw[j], &wig[(long long)e * 625 + wig_off]);
        }
        CP_COMMIT();
    }

    for (int t = beg; t < end; t++) {
        const int it = t - beg;
        const int buf = it % 3;
        CP_WAIT(1);          // group for edge t complete (for this thread)
        __syncthreads();     // visible to all; all done reading buf (it-1)%3
        if (t + 2 < end) {
            int e = g_list[t + 2];
            int b2 = (it + 2) % 3;
            CP_ASYNC16(sm0[b2], &g_m0[(long long)e * 640 + tid * 4]);
            if (wact) CP_ASYNC4(sw[b2], &wig[(long long)e * 625 + wig_off]);
        }
        CP_COMMIT();
#pragma unroll
        for (int k = 0; k < 5; k++) {
            unsigned long long b0 = *reinterpret_cast<const unsigned long long*>(
                &s_m0[buf][k * 128 + cq * 4]);
            unsigned long long b1 = *reinterpret_cast<const unsigned long long*>(
                &s_m0[buf][k * 128 + cq * 4 + 2]);
#pragma unroll
            for (int r = 0; r < 5; r++) {
                unsigned long long a2 = pack2(s_w[buf][k * 25 + iq * 5 + r]);
                fma2(acc[r][0], a2, b0);
                fma2(acc[r][1], a2, b1);
            }
        }
    }
#pragma unroll
    for (int r = 0; r < 5; r++) {
        long long off = ((long long)n * 25 + iq * 5 + r) * 128 + cq * 4;
        float4 o;
        float lo, hi;
        unpack2(acc[r][0], lo, hi); o.x = lo; o.y = hi;
        unpack2(acc[r][1], lo, hi); o.z = lo; o.w = hi;
        *reinterpret_cast<float4*>(&out[off]) = o;
    }
}

// ---------------- launch ----------------
extern "C" void kernel_launch(void* const* d_in, const int* in_sizes, int n_in,
                              void* d_out, int out_size) {
    const float* x   = (const float*)d_in[0];
    const float* xe  = (const float*)d_in[1];
    const float* ed  = (const float*)d_in[2];
    const float* wig = (const float*)d_in[3];
    const int*   ei  = (const int*)d_in[4];
    const float* w1  = (const float*)d_in[5];
    const float* b1  = (const float*)d_in[6];
    const float* g1  = (const float*)d_in[7];
    const float* be1 = (const float*)d_in[8];
    const float* w2  = (const float*)d_in[9];
    const float* b2  = (const float*)d_in[10];
    const float* g2  = (const float*)d_in[11];
    const float* be2 = (const float*)d_in[12];
    const float* w3  = (const float*)d_in[13];
    const float* b3  = (const float*)d_in[14];
    const int* noff  = (const int*)d_in[15];
    float* out = (float*)d_out;

    k_zero<<<(N_NODES + 255) / 256, 256>>>();
    k_count<<<(E_TOT + 255) / 256, 256>>>(ei, noff);
    k_scanfill<<<1, 1024>>>(ei, noff);
    k_mlp<<<E_TOT / 64, 256>>>(xe, ed, w1, b1, g1, be1, w2, b2, g2, be2, w3, b3);
    k_gather<<<N_NODES, 160>>>(x, wig, out);
    (void)in_sizes; (void)n_in; (void)out_size;
}